// round 1
// baseline (speedup 1.0000x reference)
#include <cuda_runtime.h>

// Problem constants: B=4, S=512, IN=512, OUT=112
#define BB   4
#define SS   512
#define INs  512
#define OUTs 112
#define N1   (OUTs * INs)   // 57344 = stage-1 GEMM N dimension

// Scratch (allocation-free rule: __device__ globals)
// t[b,x,o,j] : 4*512*112*512 floats = 470 MB
static __device__ float g_t[117440512];
static __device__ float g_termA[BB * SS * OUTs];   // termA[b,x,o] + bias[o]
static __device__ float g_termB[BB * SS * OUTs];   // termB[b,y,o] (from input1!)

// ---------------- f32x2 packed-FMA helpers (sm_103a FFMA2) ----------------
__device__ __forceinline__ unsigned long long pk2(float x, float y) {
    unsigned long long r;
    asm("mov.b64 %0, {%1, %2};" : "=l"(r) : "f"(x), "f"(y));
    return r;
}
__device__ __forceinline__ void fma2(unsigned long long& d,
                                     unsigned long long a,
                                     unsigned long long b) {
    asm("fma.rn.f32x2 %0, %1, %2, %0;" : "+l"(d) : "l"(a), "l"(b));
}
__device__ __forceinline__ float2 upk2(unsigned long long v) {
    float2 r;
    asm("mov.b64 {%0, %1}, %2;" : "=f"(r.x), "=f"(r.y) : "l"(v));
    return r;
}

// ---------------- Kernel 0: termA (+bias) and termB --------------------------
// termA[b,x,o] = sum_i in1[b,x,i] * w2[i,o]       + w2[2*IN, o]
// termB[b,y,o] = sum_i in1[b,y,i] * w2[IN + i, o]
// One block per (b, row); w2 (459 KB) stays hot in L2.
__global__ void terms_kernel(const float* __restrict__ in1,
                             const float* __restrict__ w2) {
    const int row = blockIdx.x;                 // b*S + x
    __shared__ float sIn[INs];
    for (int i = threadIdx.x; i < INs; i += blockDim.x)
        sIn[i] = in1[(size_t)row * INs + i];
    __syncthreads();
    const int o = threadIdx.x;
    if (o < OUTs) {
        float sA = w2[(size_t)(2 * INs) * OUTs + o];   // bias
        float sB = 0.f;
#pragma unroll 8
        for (int i = 0; i < INs; ++i) {
            const float v = sIn[i];
            sA = fmaf(v, w2[i * OUTs + o], sA);
            sB = fmaf(v, w2[(INs + i) * OUTs + o], sB);
        }
        g_termA[row * OUTs + o] = sA;
        g_termB[row * OUTs + o] = sB;
    }
}

// ---------------- Kernel 1: stage-1 SGEMM with f32x2 -------------------------
// C[2048, 57344] = A[2048, 512] @ W[512, 57344]
// A = input1 flattened (b,x); W = w1 viewed as [IN, OUT*IN] (native layout).
// 128x128 block tile, BK=8, 256 threads, 8x8 per thread, FFMA2 accumulators.
__global__ __launch_bounds__(256, 2)
void stage1_kernel(const float* __restrict__ A, const float* __restrict__ W) {
    __shared__ float As[8][128];   // transposed A tile: [k][m]
    __shared__ float Bs[8][128];   // [k][n]

    const int tid = threadIdx.x;
    const int m0 = blockIdx.y << 7;
    const int n0 = blockIdx.x << 7;

    unsigned long long acc[8][4];
#pragma unroll
    for (int i = 0; i < 8; ++i)
#pragma unroll
        for (int j = 0; j < 4; ++j) acc[i][j] = 0ull;

    const int aRow = tid >> 1;            // 0..127
    const int aCol = (tid & 1) << 2;      // 0 or 4
    const int bRow = tid >> 5;            // 0..7
    const int bCol = (tid & 31) << 2;     // 0..124

    const float* Ap = A + (size_t)(m0 + aRow) * INs + aCol;
    const float* Wp = W + (size_t)bRow * N1 + n0 + bCol;

    const int ty = tid >> 4;              // 0..15
    const int tx = tid & 15;              // 0..15

    for (int k0 = 0; k0 < INs; k0 += 8) {
        const float4 av = *(const float4*)(Ap + k0);
        const float4 bv = *(const float4*)(Wp + (size_t)k0 * N1);
        As[aCol + 0][aRow] = av.x;
        As[aCol + 1][aRow] = av.y;
        As[aCol + 2][aRow] = av.z;
        As[aCol + 3][aRow] = av.w;
        *(float4*)&Bs[bRow][bCol] = bv;
        __syncthreads();

#pragma unroll
        for (int kk = 0; kk < 8; ++kk) {
            const float4 a0 = *(const float4*)&As[kk][ty << 3];
            const float4 a1 = *(const float4*)&As[kk][(ty << 3) + 4];
            const float4 b0 = *(const float4*)&Bs[kk][tx << 3];
            const float4 b1 = *(const float4*)&Bs[kk][(tx << 3) + 4];
            const unsigned long long bp0 = pk2(b0.x, b0.y);
            const unsigned long long bp1 = pk2(b0.z, b0.w);
            const unsigned long long bp2 = pk2(b1.x, b1.y);
            const unsigned long long bp3 = pk2(b1.z, b1.w);
            const float aa[8] = {a0.x, a0.y, a0.z, a0.w, a1.x, a1.y, a1.z, a1.w};
#pragma unroll
            for (int i = 0; i < 8; ++i) {
                const unsigned long long ap = pk2(aa[i], aa[i]);
                fma2(acc[i][0], ap, bp0);
                fma2(acc[i][1], ap, bp1);
                fma2(acc[i][2], ap, bp2);
                fma2(acc[i][3], ap, bp3);
            }
        }
        __syncthreads();
    }

    float* Cp = g_t + (size_t)(m0 + (ty << 3)) * N1 + n0 + (tx << 3);
#pragma unroll
    for (int i = 0; i < 8; ++i) {
        const float2 p0 = upk2(acc[i][0]);
        const float2 p1 = upk2(acc[i][1]);
        const float2 p2 = upk2(acc[i][2]);
        const float2 p3 = upk2(acc[i][3]);
        *(float4*)(Cp + (size_t)i * N1)     = make_float4(p0.x, p0.y, p1.x, p1.y);
        *(float4*)(Cp + (size_t)i * N1 + 4) = make_float4(p2.x, p2.y, p3.x, p3.y);
    }
}

// ---------------- Kernel 2: stage-2 GEMM + epilogue --------------------------
// For each (b,x): out[b,x,y,o] = sum_j in2[b,y,j] * t[b,x,o,j]
//                              + termA[b,x,o] + termB[b,y,o]
// Per-block tile: BY=64 (y), full OUT=112 (o), BK=16. 256 threads = 16x16,
// each thread computes 4 y-rows (stride 16) x 7 o-cols (stride 16).
__global__ __launch_bounds__(256, 2)
void stage2_kernel(const float* __restrict__ in2, float* __restrict__ outp) {
    __shared__ float sA[16][64];    // in2 tile transposed: [k][y]
    __shared__ float sB[16][112];   // t tile transposed:   [k][o]

    const int tid = threadIdx.x;
    const int bx  = blockIdx.z;         // b*S + x
    const int b   = bx >> 9;
    const int y0  = blockIdx.x << 6;

    const float* tp = g_t + (size_t)bx * N1;            // [o][j], 112x512
    const float* ip = in2 + (size_t)b * SS * INs;       // [y][j], 512x512

    const int ty = tid >> 4;     // 0..15
    const int tx = tid & 15;     // 0..15

    float acc[4][7];
#pragma unroll
    for (int i = 0; i < 4; ++i)
#pragma unroll
        for (int t = 0; t < 7; ++t) acc[i][t] = 0.f;

    const int lRow = tid >> 2;           // 0..63
    const int lCol = (tid & 3) << 2;     // 0,4,8,12

    for (int k0 = 0; k0 < INs; k0 += 16) {
        // load in2 tile [64 x 16] (float4, coalesced), store transposed
        const float4 av = *(const float4*)(ip + (size_t)(y0 + lRow) * INs + k0 + lCol);
        sA[lCol + 0][lRow] = av.x;
        sA[lCol + 1][lRow] = av.y;
        sA[lCol + 2][lRow] = av.z;
        sA[lCol + 3][lRow] = av.w;
        // load t tile [112 x 16] (448 float4 slots over 256 threads)
#pragma unroll
        for (int it = 0; it < 2; ++it) {
            const int idx = tid + (it << 8);
            if (idx < 448) {
                const int o = idx >> 2;
                const int c = (idx & 3) << 2;
                const float4 bv = *(const float4*)(tp + (size_t)o * INs + k0 + c);
                sB[c + 0][o] = bv.x;
                sB[c + 1][o] = bv.y;
                sB[c + 2][o] = bv.z;
                sB[c + 3][o] = bv.w;
            }
        }
        __syncthreads();

#pragma unroll
        for (int kk = 0; kk < 16; ++kk) {
            const float a0 = sA[kk][ty];
            const float a1 = sA[kk][ty + 16];
            const float a2 = sA[kk][ty + 32];
            const float a3 = sA[kk][ty + 48];
            float bb[7];
#pragma unroll
            for (int t = 0; t < 7; ++t) bb[t] = sB[kk][tx + 16 * t];
#pragma unroll
            for (int t = 0; t < 7; ++t) {
                acc[0][t] = fmaf(a0, bb[t], acc[0][t]);
                acc[1][t] = fmaf(a1, bb[t], acc[1][t]);
                acc[2][t] = fmaf(a2, bb[t], acc[2][t]);
                acc[3][t] = fmaf(a3, bb[t], acc[3][t]);
            }
        }
        __syncthreads();
    }

    // epilogue: + termA[b,x,o] + termB[b,y,o]
    const float* tA     = g_termA + (size_t)bx * OUTs;
    const float* tBbase = g_termB + ((size_t)b * SS) * OUTs;
    float* op = outp + (size_t)bx * SS * OUTs;

    float ta[7];
#pragma unroll
    for (int t = 0; t < 7; ++t) ta[t] = tA[tx + 16 * t];

#pragma unroll
    for (int i = 0; i < 4; ++i) {
        const int y = y0 + ty + 16 * i;
        const float* tB = tBbase + (size_t)y * OUTs;
        float* orow = op + (size_t)y * OUTs;
#pragma unroll
        for (int t = 0; t < 7; ++t) {
            const int o = tx + 16 * t;
            orow[o] = acc[i][t] + ta[t] + tB[o];
        }
    }
}

// ---------------- launch -----------------------------------------------------
extern "C" void kernel_launch(void* const* d_in, const int* in_sizes, int n_in,
                              void* d_out, int out_size) {
    const float* in1 = (const float*)d_in[0];   // (4,512,512)
    const float* in2 = (const float*)d_in[1];   // (4,512,512)
    const float* w1  = (const float*)d_in[2];   // (512,112,512)
    const float* w2  = (const float*)d_in[3];   // (1025,112)
    float* out = (float*)d_out;                 // (4,512,512,112)

    terms_kernel<<<BB * SS, 128>>>(in1, w2);

    dim3 g1(N1 / 128, (BB * SS) / 128);         // (448, 16)
    stage1_kernel<<<g1, 256>>>(in1, w1);

    dim3 g2(SS / 64, 1, BB * SS);               // (8, 1, 2048)
    stage2_kernel<<<g2, 256>>>(in2, out);
}